// round 12
// baseline (speedup 1.0000x reference)
#include <cuda_runtime.h>
#include <cuda_fp16.h>
#include <math.h>
#include <stdint.h>

#define B_   8
#define S_   512
#define HID_ 768
#define H_   12
#define D_   64
#define BS_  (B_*S_)          // 4096
#define BH_  (B_*H_)          // 96

#define CTX_ELEMS ((size_t)B_*S_*HID_)        // 3,145,728
#define SC_ELEMS  ((size_t)BH_*S_*S_)         // 25,165,824

#define NHID ((size_t)BS_*HID_)               // 3,145,728
#define NW   ((size_t)HID_*HID_)              //   589,824
#define ROWP (HID_/2)                         // 384 pairs per W row

// Scratch (device globals — no allocation in kernel_launch)
// g_q/g_k/g_v use FRAGMENT-PAIRED d-layout: within each 8-col group,
// physical order [c0,c4,c1,c5,c2,c6,c3,c7] so (c,c+4) pairs are adjacent.
__device__ float g_q[BH_*S_*D_];
__device__ float g_k[BH_*S_*D_];
__device__ float g_v[BH_*S_*D_];
__device__ __half g_hidH[NHID];               // hidden: fp16 hi plane only
__device__ uint2  g_WPf[3][NW/2];             // W: (f16x2 hi, f16x2 lo) per pair

__device__ __forceinline__ float to_tf32(float x) {
    float r;
    asm("cvt.rna.tf32.f32 %0, %1;" : "=f"(r) : "f"(x));
    return r;
}

__device__ __forceinline__ void mma_tf32(float* c, const uint32_t* a, const uint32_t* b) {
    asm volatile(
        "mma.sync.aligned.m16n8k8.row.col.f32.tf32.tf32.f32 "
        "{%0,%1,%2,%3}, {%4,%5,%6,%7}, {%8,%9}, {%0,%1,%2,%3};\n"
        : "+f"(c[0]), "+f"(c[1]), "+f"(c[2]), "+f"(c[3])
        : "r"(a[0]), "r"(a[1]), "r"(a[2]), "r"(a[3]), "r"(b[0]), "r"(b[1]));
}

__device__ __forceinline__ void mma_f16(float* c, const uint32_t* a, const uint32_t* b) {
    asm volatile(
        "mma.sync.aligned.m16n8k16.row.col.f32.f16.f16.f32 "
        "{%0,%1,%2,%3}, {%4,%5,%6,%7}, {%8,%9}, {%0,%1,%2,%3};\n"
        : "+f"(c[0]), "+f"(c[1]), "+f"(c[2]), "+f"(c[3])
        : "r"(a[0]), "r"(a[1]), "r"(a[2]), "r"(a[3]), "r"(b[0]), "r"(b[1]));
}

__device__ __forceinline__ uint32_t smem_u32(const void* p) {
    return (uint32_t)__cvta_generic_to_shared(p);
}

__device__ __forceinline__ void cp16(uint32_t dst, const void* src) {
    asm volatile("cp.async.ca.shared.global [%0], [%1], 16;\n" :: "r"(dst), "l"(src));
}

// ---------------------------------------------------------------------------
// Kernel 0: prep. hidden -> fp16 hi plane; W -> fp16 (hi,lo) pair format.
// [R11 exact]
// ---------------------------------------------------------------------------
#define A_THREADS (NHID / 8)                  // 393,216
#define W_THREADS (3 * NW / 8)                // 221,184
#define PREP_BLOCKS (int)((A_THREADS + W_THREADS) / 256)   // 2400

__global__ void __launch_bounds__(256)
split_prep(const float* __restrict__ hid, const float* __restrict__ Wq,
           const float* __restrict__ Wk,  const float* __restrict__ Wv)
{
    size_t i = (size_t)blockIdx.x * 256 + threadIdx.x;
    if (i < A_THREADS) {
        size_t base = i * 8;
        float4 v0 = *(const float4*)(hid + base);
        float4 v1 = *(const float4*)(hid + base + 4);
        __half2 o[4];
        o[0] = __half2(__float2half_rn(v0.x), __float2half_rn(v0.y));
        o[1] = __half2(__float2half_rn(v0.z), __float2half_rn(v0.w));
        o[2] = __half2(__float2half_rn(v1.x), __float2half_rn(v1.y));
        o[3] = __half2(__float2half_rn(v1.z), __float2half_rn(v1.w));
        *(uint4*)(g_hidH + base) = *(uint4*)o;
    } else {
        size_t j = i - A_THREADS;
        int w = (int)(j / (NW / 8));
        size_t o8 = (j - (size_t)w * (NW / 8)) * 8;
        const float* W = (w == 0) ? Wq : ((w == 1) ? Wk : Wv);
        float4 v0 = *(const float4*)(W + o8);
        float4 v1 = *(const float4*)(W + o8 + 4);
        float f[8] = {v0.x, v0.y, v0.z, v0.w, v1.x, v1.y, v1.z, v1.w};
        uint2 p[4];
        #pragma unroll
        for (int q = 0; q < 4; q++) {
            __half h0 = __float2half_rn(f[2*q]);
            __half h1 = __float2half_rn(f[2*q+1]);
            __half2 hh = __half2(h0, h1);
            __half2 ll = __half2(__float2half_rn(f[2*q]   - __half2float(h0)),
                                 __float2half_rn(f[2*q+1] - __half2float(h1)));
            p[q].x = *(uint32_t*)&hh;
            p[q].y = *(uint32_t*)&ll;
        }
        uint2* dst = g_WPf[w] + o8 / 2;
        *(uint4*)dst       = *(uint4*)&p[0];
        *(uint4*)(dst + 2) = *(uint4*)&p[2];
    }
}

// ---------------------------------------------------------------------------
// Kernel 1: QKV projection via fp16 2-term MMA. [R11 loop exact]
// Epilogue: + bias, tf32 round, PAIRED-d scatter to [B,H,S,D].
// ---------------------------------------------------------------------------
__global__ void __launch_bounds__(256, 2)
qkv_mma(const float* __restrict__ bq, const float* __restrict__ bk,
        const float* __restrict__ bv)
{
    const int z = blockIdx.z;
    const uint2* Wp   = g_WPf[z];
    const float* bias = (z == 0) ? bq : ((z == 1) ? bk : bv);
    float* out        = (z == 0) ? g_q : ((z == 1) ? g_k : g_v);

    const int m0 = blockIdx.y * 128;
    const int n0 = blockIdx.x * 128;

    __shared__ __align__(16) uint32_t As[2][128][20];
    __shared__ __align__(16) uint32_t Bs[2][128][40];

    const int tid  = threadIdx.x;
    const int lane = tid & 31;
    const int wid  = tid >> 5;
    const int gr   = lane >> 2;
    const int gc   = lane & 3;
    const int wm   = (wid & 1) * 64;
    const int wn   = (wid >> 1) * 32;

    float c[4][4][4];
    #pragma unroll
    for (int im = 0; im < 4; im++)
        #pragma unroll
        for (int jn = 0; jn < 4; jn++)
            #pragma unroll
            for (int r = 0; r < 4; r++) c[im][jn][r] = 0.0f;

    #define LOAD_STAGE(buf, it_)                                                 \
    {                                                                            \
        _Pragma("unroll")                                                        \
        for (int r = 0; r < 2; r++) {                                            \
            int cc = tid + 256 * r; int row = cc >> 2; int sub = cc & 3;         \
            cp16(smem_u32(&As[buf][row][sub * 4]),                               \
                 g_hidH + (size_t)(m0 + row) * HID_ + (it_) * 32 + sub * 8);     \
        }                                                                        \
        _Pragma("unroll")                                                        \
        for (int r = 0; r < 4; r++) {                                            \
            int cc = tid + 256 * r; int row = cc >> 3; int sub = cc & 7;         \
            cp16(smem_u32(&Bs[buf][row][sub * 4]),                               \
                 Wp + (size_t)(n0 + row) * ROWP + (it_) * 16 + sub * 2);         \
        }                                                                        \
        asm volatile("cp.async.commit_group;\n");                                \
    }

    LOAD_STAGE(0, 0)

    const int NIT = HID_ / 32;   // 24 stages of k32
    for (int it = 0; it < NIT; it++) {
        asm volatile("cp.async.wait_group 0;\n");
        __syncthreads();
        if (it + 1 < NIT) { LOAD_STAGE((it + 1) & 1, it + 1) }

        const int buf = it & 1;
        #pragma unroll
        for (int ks = 0; ks < 2; ks++) {
            const int acol = 8 * ks + gc;
            const int c0   = 16 * ks + 2 * gc;
            uint32_t a[4][4], bhi[4][2], blo[4][2];
            #pragma unroll
            for (int im = 0; im < 4; im++) {
                int r = wm + im * 16 + gr;
                a[im][0] = As[buf][r    ][acol    ];
                a[im][1] = As[buf][r + 8][acol    ];
                a[im][2] = As[buf][r    ][acol + 4];
                a[im][3] = As[buf][r + 8][acol + 4];
            }
            #pragma unroll
            for (int jn = 0; jn < 4; jn++) {
                int n = wn + jn * 8 + gr;
                uint2 t0 = *(const uint2*)&Bs[buf][n][c0    ];
                uint2 t1 = *(const uint2*)&Bs[buf][n][c0 + 8];
                bhi[jn][0] = t0.x; bhi[jn][1] = t1.x;
                blo[jn][0] = t0.y; blo[jn][1] = t1.y;
            }
            #pragma unroll
            for (int im = 0; im < 4; im++)
                #pragma unroll
                for (int jn = 0; jn < 4; jn++)
                    mma_f16(c[im][jn], a[im], bhi[jn]);
            #pragma unroll
            for (int im = 0; im < 4; im++)
                #pragma unroll
                for (int jn = 0; jn < 4; jn++)
                    mma_f16(c[im][jn], a[im], blo[jn]);
        }
        __syncthreads();
    }
    #undef LOAD_STAGE

    // Epilogue: + bias, tf32 round, paired-d scatter.
    // logical cols (2gc, 2gc+1) -> physical (p0, p0+2), p0 = gc<2 ? 4gc : 4gc-7
    const int h      = (n0 + wn) >> 6;
    const int d_base = (n0 + wn) & 63;
    const int p0     = (gc < 2) ? 4 * gc : 4 * gc - 7;
    #pragma unroll
    for (int jn = 0; jn < 4; jn++) {
        int og = d_base + jn * 8;
        float b0 = bias[n0 + wn + jn * 8 + gc * 2];
        float b1 = bias[n0 + wn + jn * 8 + gc * 2 + 1];
        #pragma unroll
        for (int im = 0; im < 4; im++) {
            int m = m0 + wm + im * 16 + gr;
            int b = m >> 9;
            int s = m & 511;
            float* o = out + (((size_t)(b * H_ + h) * S_ + s) * D_ + og);
            o[p0]     = to_tf32(c[im][jn][0] + b0);
            o[p0 + 2] = to_tf32(c[im][jn][1] + b1);
            float* o2 = o + 8 * D_;
            o2[p0]     = to_tf32(c[im][jn][2] + b0);
            o2[p0 + 2] = to_tf32(c[im][jn][3] + b1);
        }
    }
}

// ---------------------------------------------------------------------------
// Kernel 2: self-similarity scores (qq, kk, vv) via tf32 mma.
// Inputs paired-d -> fragment loads are conflict-free LDS.64 (stride 72).
// Block: 64(q) x 128(k), 256 threads (8 warps 2x4). grid: (4, 8, 3*96).
// ---------------------------------------------------------------------------
__global__ void __launch_bounds__(256)
scores_sim(const float* __restrict__ mask, float* __restrict__ out_base)
{
    const int z    = blockIdx.z;
    const int type = 1 + z / BH_;       // 1:qq 2:kk 3:vv
    const int bh   = z % BH_;

    const float* X = (type == 1) ? g_q : ((type == 2) ? g_k : g_v);
    X += (size_t)bh * S_ * D_;

    float* out = out_base + (size_t)type * SC_ELEMS + (size_t)bh * S_ * S_;
    const float* mrow = mask + (size_t)(bh / H_) * S_;

    const int m0 = blockIdx.y * 64;
    const int n0 = blockIdx.x * 128;

    __shared__ float Xs[64][72];
    __shared__ float Ys[128][72];

    const int tid = threadIdx.x;

    #pragma unroll
    for (int r = 0; r < 4; r++) {
        int idx = tid + 256 * r;
        int row = idx >> 4;
        int q   = idx & 15;
        *(float4*)&Xs[row][q * 4] = *(const float4*)(X + (size_t)(m0 + row) * D_ + q * 4);
    }
    #pragma unroll
    for (int r = 0; r < 8; r++) {
        int idx = tid + 256 * r;
        int row = idx >> 4;
        int q   = idx & 15;
        *(float4*)&Ys[row][q * 4] = *(const float4*)(X + (size_t)(n0 + row) * D_ + q * 4);
    }
    __syncthreads();

    const int lane = tid & 31;
    const int wid  = tid >> 5;
    const int wm   = (wid & 1) * 32;
    const int wn   = (wid >> 1) * 32;
    const int gr   = lane >> 2;
    const int gc   = lane & 3;

    float c[2][4][4];
    #pragma unroll
    for (int im = 0; im < 2; im++)
        #pragma unroll
        for (int jn = 0; jn < 4; jn++)
            #pragma unroll
            for (int r = 0; r < 4; r++) c[im][jn][r] = 0.0f;

    #pragma unroll
    for (int k0 = 0; k0 < 64; k0 += 8) {
        const int pc = k0 + 2 * gc;         // paired col: (.x=k0+gc, .y=k0+gc+4)
        uint32_t a[2][4], b[4][2];
        #pragma unroll
        for (int im = 0; im < 2; im++) {
            int r0 = wm + im * 16 + gr;
            float2 t0 = *(const float2*)&Xs[r0    ][pc];
            float2 t1 = *(const float2*)&Xs[r0 + 8][pc];
            a[im][0] = __float_as_uint(t0.x);
            a[im][1] = __float_as_uint(t1.x);
            a[im][2] = __float_as_uint(t0.y);
            a[im][3] = __float_as_uint(t1.y);
        }
        #pragma unroll
        for (int jn = 0; jn < 4; jn++) {
            int n = wn + jn * 8 + gr;
            float2 t = *(const float2*)&Ys[n][pc];
            b[jn][0] = __float_as_uint(t.x);
            b[jn][1] = __float_as_uint(t.y);
        }
        #pragma unroll
        for (int im = 0; im < 2; im++)
            #pragma unroll
            for (int jn = 0; jn < 4; jn++)
                mma_tf32(c[im][jn], a[im], b[jn]);
    }

    #pragma unroll
    for (int im = 0; im < 2; im++) {
        #pragma unroll
        for (int jn = 0; jn < 4; jn++) {
            int row = m0 + wm + im * 16 + gr;
            int col = n0 + wn + jn * 8 + gc * 2;
            float mv0 = mrow[col], mv1 = mrow[col + 1];
            float2 o0 = make_float2(c[im][jn][0] * 0.125f + mv0,
                                    c[im][jn][1] * 0.125f + mv1);
            float2 o1 = make_float2(c[im][jn][2] * 0.125f + mv0,
                                    c[im][jn][3] * 0.125f + mv1);
            *(float2*)(out + (size_t)row * S_ + col)       = o0;
            *(float2*)(out + (size_t)(row + 8) * S_ + col) = o1;
        }
    }
}

// ---------------------------------------------------------------------------
// Kernel 3: fused qk-scores + softmax + P@V, all-MMA (tf32).
// Q/K paired-d: S-phase fragment loads are LDS.64. V O-phase unchanged
// (k-dim = kv rows); output cols physical -> un-paired in ctx epilogue.
// 128 threads = 4 warps. grid: (8, 96).
// ---------------------------------------------------------------------------
__global__ void __launch_bounds__(128)
flash_attn(const float* __restrict__ mask, float* __restrict__ sout_base,
           float* __restrict__ ctx)
{
    const int bh = blockIdx.y;
    const int q0 = blockIdx.x * 64;
    const int b  = bh / H_;
    const int h  = bh - b * H_;
    const float* Qp = g_q + (size_t)bh * S_ * D_;
    const float* Kp = g_k + (size_t)bh * S_ * D_;
    const float* Vp = g_v + (size_t)bh * S_ * D_;
    float* sout = sout_base + (size_t)bh * S_ * S_;
    const float* mrow = mask + (size_t)b * S_;

    __shared__ float QPs[64][72];   // Q tile (paired-d), then reused as P tile
    __shared__ float Ks[64][72];    // paired-d
    __shared__ float Vs[64][72];    // paired-d (cols physical)

    const int tid  = threadIdx.x;
    const int lane = tid & 31;
    const int w    = tid >> 5;
    const int gr   = lane >> 2;
    const int gc   = lane & 3;

    #pragma unroll
    for (int r = 0; r < 8; r++) {
        int idx = tid + 128 * r;
        int row = idx >> 4;
        int q   = idx & 15;
        *(float4*)&QPs[row][q * 4] =
            *(const float4*)(Qp + (size_t)(q0 + row) * D_ + q * 4);
    }
    __syncthreads();

    uint32_t aq[8][4];
    #pragma unroll
    for (int ks = 0; ks < 8; ks++) {
        int r0 = w * 16 + gr;
        float2 t0 = *(const float2*)&QPs[r0    ][8 * ks + 2 * gc];
        float2 t1 = *(const float2*)&QPs[r0 + 8][8 * ks + 2 * gc];
        aq[ks][0] = __float_as_uint(t0.x);
        aq[ks][1] = __float_as_uint(t1.x);
        aq[ks][2] = __float_as_uint(t0.y);
        aq[ks][3] = __float_as_uint(t1.y);
    }

    float o[8][4];
    #pragma unroll
    for (int jd = 0; jd < 8; jd++)
        #pragma unroll
        for (int r = 0; r < 4; r++) o[jd][r] = 0.0f;

    float m0 = -1e30f, m1 = -1e30f, l0 = 0.0f, l1 = 0.0f;
    const int rowg = q0 + w * 16 + gr;

    for (int kt = 0; kt < 8; kt++) {
        #pragma unroll
        for (int r = 0; r < 8; r++) {
            int idx = tid + 128 * r;
            int row = idx >> 4;
            int q   = idx & 15;
            *(float4*)&Ks[row][q * 4] =
                *(const float4*)(Kp + (size_t)(kt*64 + row) * D_ + q * 4);
            *(float4*)&Vs[row][q * 4] =
                *(const float4*)(Vp + (size_t)(kt*64 + row) * D_ + q * 4);
        }
        __syncthreads();

        float s[8][4];
        #pragma unroll
        for (int jn = 0; jn < 8; jn++) {
            #pragma unroll
            for (int r = 0; r < 4; r++) s[jn][r] = 0.0f;
            #pragma unroll
            for (int ks = 0; ks < 8; ks++) {
                float2 t = *(const float2*)&Ks[jn*8 + gr][8 * ks + 2 * gc];
                uint32_t bv[2];
                bv[0] = __float_as_uint(t.x);
                bv[1] = __float_as_uint(t.y);
                mma_tf32(s[jn], aq[ks], bv);
            }
        }

        float mx0 = -1e30f, mx1 = -1e30f;
        #pragma unroll
        for (int jn = 0; jn < 8; jn++) {
            int col = kt*64 + jn*8 + gc*2;
            float mv0 = mrow[col], mv1 = mrow[col + 1];
            s[jn][0] = s[jn][0]*0.125f + mv0;  s[jn][1] = s[jn][1]*0.125f + mv1;
            s[jn][2] = s[jn][2]*0.125f + mv0;  s[jn][3] = s[jn][3]*0.125f + mv1;
            *(float2*)(sout + (size_t)rowg       * S_ + col) = make_float2(s[jn][0], s[jn][1]);
            *(float2*)(sout + (size_t)(rowg + 8) * S_ + col) = make_float2(s[jn][2], s[jn][3]);
            mx0 = fmaxf(mx0, fmaxf(s[jn][0], s[jn][1]));
            mx1 = fmaxf(mx1, fmaxf(s[jn][2], s[jn][3]));
        }
        mx0 = fmaxf(mx0, __shfl_xor_sync(0xffffffffu, mx0, 1));
        mx0 = fmaxf(mx0, __shfl_xor_sync(0xffffffffu, mx0, 2));
        mx1 = fmaxf(mx1, __shfl_xor_sync(0xffffffffu, mx1, 1));
        mx1 = fmaxf(mx1, __shfl_xor_sync(0xffffffffu, mx1, 2));

        float mn0 = fmaxf(m0, mx0), mn1 = fmaxf(m1, mx1);
        float sc0 = __expf(m0 - mn0), sc1 = __expf(m1 - mn1);

        float ps0 = 0.0f, ps1 = 0.0f;
        #pragma unroll
        for (int jn = 0; jn < 8; jn++) {
            float p0 = __expf(s[jn][0] - mn0), p1 = __expf(s[jn][1] - mn0);
            float p2 = __expf(s[jn][2] - mn1), p3 = __expf(s[jn][3] - mn1);
            ps0 += p0 + p1;  ps1 += p2 + p3;
            int col = jn*8 + gc*2;
            int r0  = w*16 + gr;
            *(float2*)&QPs[r0    ][col] = make_float2(to_tf32(p0), to_tf32(p1));
            *(float2*)&QPs[r0 + 8][col] = make_float2(to_tf32(p2), to_tf32(p3));
        }
        ps0 += __shfl_xor_sync(0xffffffffu, ps0, 1);
        ps0 += __shfl_xor_sync(0xffffffffu, ps0, 2);
        ps1 += __shfl_xor_sync(0xffffffffu, ps1, 1);
        ps1 += __shfl_xor_sync(0xffffffffu, ps1, 2);
        l0 = l0 * sc0 + ps0;  l1 = l1 * sc1 + ps1;
        m0 = mn0;  m1 = mn1;

        #pragma unroll
        for (int jd = 0; jd < 8; jd++) {
            o[jd][0] *= sc0;  o[jd][1] *= sc0;
            o[jd][2] *= sc1;  o[jd][3] *= sc1;
        }
        __syncwarp();

        // O += P @ V  (V rows = kv dim: indexing unchanged; cols physical-d)
        #pragma unroll
        for (int ks = 0; ks < 8; ks++) {
            uint32_t ap[4];
            int r0 = w*16 + gr;
            ap[0] = __float_as_uint(QPs[r0    ][8*ks + gc    ]);
            ap[1] = __float_as_uint(QPs[r0 + 8][8*ks + gc    ]);
            ap[2] = __float_as_uint(QPs[r0    ][8*ks + gc + 4]);
            ap[3] = __float_as_uint(QPs[r0 + 8][8*ks + gc + 4]);
            #pragma unroll
            for (int jd = 0; jd < 8; jd++) {
                uint32_t bv[2];
                bv[0] = __float_as_uint(Vs[8*ks + gc    ][jd*8 + gr]);
                bv[1] = __float_as_uint(Vs[8*ks + gc + 4][jd*8 + gr]);
                mma_tf32(o[jd], ap, bv);
            }
        }
        __syncthreads();
    }

    // ctx epilogue: output cols are PHYSICAL (paired) -> logical (gc, gc+4)
    float i0 = 1.0f / l0, i1 = 1.0f / l1;
    #pragma unroll
    for (int jd = 0; jd < 8; jd++) {
        int d0 = jd*8 + gc;          // physical 2gc   -> logical gc
        int d1 = jd*8 + gc + 4;      // physical 2gc+1 -> logical gc+4
        float* op = ctx + ((size_t)(b * S_ + rowg) * HID_ + h * D_);
        op[d0] = o[jd][0] * i0;
        op[d1] = o[jd][1] * i0;
        float* op2 = op + 8 * HID_;
        op2[d0] = o[jd][2] * i1;
        op2[d1] = o[jd][3] * i1;
    }
}

// ---------------------------------------------------------------------------
extern "C" void kernel_launch(void* const* d_in, const int* in_sizes, int n_in,
                              void* d_out, int out_size)
{
    const float* hid  = (const float*)d_in[0];
    const float* mask = (const float*)d_in[1];
    const float* Wq   = (const float*)d_in[2];
    const float* bq   = (const float*)d_in[3];
    const float* Wk   = (const float*)d_in[4];
    const float* bk   = (const float*)d_in[5];
    const float* Wv   = (const float*)d_in[6];
    const float* bv   = (const float*)d_in[7];
    float* out = (float*)d_out;

    // 0) prep: hidden -> fp16 hi plane; W -> fp16 (hi,lo) pairs
    split_prep<<<PREP_BLOCKS, 256>>>(hid, Wq, Wk, Wv);

    // 1) Q,K,V projections (fp16 2-term MMA, paired-d tf32 outputs)
    qkv_mma<<<dim3(HID_ / 128, BS_ / 128, 3), 256>>>(bq, bk, bv);

    // 2) qq / kk / vv self-similarity scores (paired LDS.64 fragments)
    scores_sim<<<dim3(S_ / 128, S_ / 64, 3 * BH_), 256>>>(mask, out + CTX_ELEMS);

    // 3) fused qk scores + softmax + P@V -> scores(qk) region + ctx
    flash_attn<<<dim3(S_ / 64, BH_), 128>>>(mask, out + CTX_ELEMS, out);
}

// round 13
// speedup vs baseline: 1.2828x; 1.2828x over previous
#include <cuda_runtime.h>
#include <cuda_fp16.h>
#include <math.h>
#include <stdint.h>

#define B_   8
#define S_   512
#define HID_ 768
#define H_   12
#define D_   64
#define BS_  (B_*S_)          // 4096
#define BH_  (B_*H_)          // 96

#define CTX_ELEMS ((size_t)B_*S_*HID_)        // 3,145,728
#define SC_ELEMS  ((size_t)BH_*S_*S_)         // 25,165,824

#define NHID ((size_t)BS_*HID_)               // 3,145,728
#define NW   ((size_t)HID_*HID_)              //   589,824
#define ROWP (HID_/2)                         // 384 pairs per W row

// Scratch (device globals — no allocation in kernel_launch)
__device__ __half g_qh[BH_*S_*D_];            // q,k,v in fp16 (roundoff = tf32's)
__device__ __half g_kh[BH_*S_*D_];
__device__ __half g_vh[BH_*S_*D_];
__device__ float  g_v [BH_*S_*D_];            // V fp32 (tf32-rounded) for O-phase
__device__ __half g_hidH[NHID];               // hidden: fp16 hi plane only
__device__ uint2  g_WPf[3][NW/2];             // W: (f16x2 hi, f16x2 lo) per pair

__device__ __forceinline__ float to_tf32(float x) {
    float r;
    asm("cvt.rna.tf32.f32 %0, %1;" : "=f"(r) : "f"(x));
    return r;
}

__device__ __forceinline__ void mma_tf32(float* c, const uint32_t* a, const uint32_t* b) {
    asm volatile(
        "mma.sync.aligned.m16n8k8.row.col.f32.tf32.tf32.f32 "
        "{%0,%1,%2,%3}, {%4,%5,%6,%7}, {%8,%9}, {%0,%1,%2,%3};\n"
        : "+f"(c[0]), "+f"(c[1]), "+f"(c[2]), "+f"(c[3])
        : "r"(a[0]), "r"(a[1]), "r"(a[2]), "r"(a[3]), "r"(b[0]), "r"(b[1]));
}

__device__ __forceinline__ void mma_f16(float* c, const uint32_t* a, const uint32_t* b) {
    asm volatile(
        "mma.sync.aligned.m16n8k16.row.col.f32.f16.f16.f32 "
        "{%0,%1,%2,%3}, {%4,%5,%6,%7}, {%8,%9}, {%0,%1,%2,%3};\n"
        : "+f"(c[0]), "+f"(c[1]), "+f"(c[2]), "+f"(c[3])
        : "r"(a[0]), "r"(a[1]), "r"(a[2]), "r"(a[3]), "r"(b[0]), "r"(b[1]));
}

__device__ __forceinline__ uint32_t smem_u32(const void* p) {
    return (uint32_t)__cvta_generic_to_shared(p);
}

__device__ __forceinline__ void cp16(uint32_t dst, const void* src) {
    asm volatile("cp.async.ca.shared.global [%0], [%1], 16;\n" :: "r"(dst), "l"(src));
}

// ---------------------------------------------------------------------------
// Kernel 0: prep. hidden -> fp16 hi plane; W -> fp16 (hi,lo) pairs. [R11 exact]
// ---------------------------------------------------------------------------
#define A_THREADS (NHID / 8)                  // 393,216
#define W_THREADS (3 * NW / 8)                // 221,184
#define PREP_BLOCKS (int)((A_THREADS + W_THREADS) / 256)   // 2400

__global__ void __launch_bounds__(256)
split_prep(const float* __restrict__ hid, const float* __restrict__ Wq,
           const float* __restrict__ Wk,  const float* __restrict__ Wv)
{
    size_t i = (size_t)blockIdx.x * 256 + threadIdx.x;
    if (i < A_THREADS) {
        size_t base = i * 8;
        float4 v0 = *(const float4*)(hid + base);
        float4 v1 = *(const float4*)(hid + base + 4);
        __half2 o[4];
        o[0] = __half2(__float2half_rn(v0.x), __float2half_rn(v0.y));
        o[1] = __half2(__float2half_rn(v0.z), __float2half_rn(v0.w));
        o[2] = __half2(__float2half_rn(v1.x), __float2half_rn(v1.y));
        o[3] = __half2(__float2half_rn(v1.z), __float2half_rn(v1.w));
        *(uint4*)(g_hidH + base) = *(uint4*)o;
    } else {
        size_t j = i - A_THREADS;
        int w = (int)(j / (NW / 8));
        size_t o8 = (j - (size_t)w * (NW / 8)) * 8;
        const float* W = (w == 0) ? Wq : ((w == 1) ? Wk : Wv);
        float4 v0 = *(const float4*)(W + o8);
        float4 v1 = *(const float4*)(W + o8 + 4);
        float f[8] = {v0.x, v0.y, v0.z, v0.w, v1.x, v1.y, v1.z, v1.w};
        uint2 p[4];
        #pragma unroll
        for (int q = 0; q < 4; q++) {
            __half h0 = __float2half_rn(f[2*q]);
            __half h1 = __float2half_rn(f[2*q+1]);
            __half2 hh = __half2(h0, h1);
            __half2 ll = __half2(__float2half_rn(f[2*q]   - __half2float(h0)),
                                 __float2half_rn(f[2*q+1] - __half2float(h1)));
            p[q].x = *(uint32_t*)&hh;
            p[q].y = *(uint32_t*)&ll;
        }
        uint2* dst = g_WPf[w] + o8 / 2;
        *(uint4*)dst       = *(uint4*)&p[0];
        *(uint4*)(dst + 2) = *(uint4*)&p[2];
    }
}

// ---------------------------------------------------------------------------
// Kernel 1: QKV projection via fp16 2-term MMA. [R11 loop exact]
// Epilogue: + bias, write fp16 q/k/v; additionally tf32-fp32 copy of V.
// ---------------------------------------------------------------------------
__global__ void __launch_bounds__(256, 2)
qkv_mma(const float* __restrict__ bq, const float* __restrict__ bk,
        const float* __restrict__ bv)
{
    const int z = blockIdx.z;
    const uint2* Wp   = g_WPf[z];
    const float* bias = (z == 0) ? bq : ((z == 1) ? bk : bv);
    __half* outh      = (z == 0) ? g_qh : ((z == 1) ? g_kh : g_vh);

    const int m0 = blockIdx.y * 128;
    const int n0 = blockIdx.x * 128;

    __shared__ __align__(16) uint32_t As[2][128][20];
    __shared__ __align__(16) uint32_t Bs[2][128][40];

    const int tid  = threadIdx.x;
    const int lane = tid & 31;
    const int wid  = tid >> 5;
    const int gr   = lane >> 2;
    const int gc   = lane & 3;
    const int wm   = (wid & 1) * 64;
    const int wn   = (wid >> 1) * 32;

    float c[4][4][4];
    #pragma unroll
    for (int im = 0; im < 4; im++)
        #pragma unroll
        for (int jn = 0; jn < 4; jn++)
            #pragma unroll
            for (int r = 0; r < 4; r++) c[im][jn][r] = 0.0f;

    #define LOAD_STAGE(buf, it_)                                                 \
    {                                                                            \
        _Pragma("unroll")                                                        \
        for (int r = 0; r < 2; r++) {                                            \
            int cc = tid + 256 * r; int row = cc >> 2; int sub = cc & 3;         \
            cp16(smem_u32(&As[buf][row][sub * 4]),                               \
                 g_hidH + (size_t)(m0 + row) * HID_ + (it_) * 32 + sub * 8);     \
        }                                                                        \
        _Pragma("unroll")                                                        \
        for (int r = 0; r < 4; r++) {                                            \
            int cc = tid + 256 * r; int row = cc >> 3; int sub = cc & 7;         \
            cp16(smem_u32(&Bs[buf][row][sub * 4]),                               \
                 Wp + (size_t)(n0 + row) * ROWP + (it_) * 16 + sub * 2);         \
        }                                                                        \
        asm volatile("cp.async.commit_group;\n");                                \
    }

    LOAD_STAGE(0, 0)

    const int NIT = HID_ / 32;   // 24 stages of k32
    for (int it = 0; it < NIT; it++) {
        asm volatile("cp.async.wait_group 0;\n");
        __syncthreads();
        if (it + 1 < NIT) { LOAD_STAGE((it + 1) & 1, it + 1) }

        const int buf = it & 1;
        #pragma unroll
        for (int ks = 0; ks < 2; ks++) {
            const int acol = 8 * ks + gc;
            const int c0   = 16 * ks + 2 * gc;
            uint32_t a[4][4], bhi[4][2], blo[4][2];
            #pragma unroll
            for (int im = 0; im < 4; im++) {
                int r = wm + im * 16 + gr;
                a[im][0] = As[buf][r    ][acol    ];
                a[im][1] = As[buf][r + 8][acol    ];
                a[im][2] = As[buf][r    ][acol + 4];
                a[im][3] = As[buf][r + 8][acol + 4];
            }
            #pragma unroll
            for (int jn = 0; jn < 4; jn++) {
                int n = wn + jn * 8 + gr;
                uint2 t0 = *(const uint2*)&Bs[buf][n][c0    ];
                uint2 t1 = *(const uint2*)&Bs[buf][n][c0 + 8];
                bhi[jn][0] = t0.x; bhi[jn][1] = t1.x;
                blo[jn][0] = t0.y; blo[jn][1] = t1.y;
            }
            #pragma unroll
            for (int im = 0; im < 4; im++)
                #pragma unroll
                for (int jn = 0; jn < 4; jn++)
                    mma_f16(c[im][jn], a[im], bhi[jn]);
            #pragma unroll
            for (int im = 0; im < 4; im++)
                #pragma unroll
                for (int jn = 0; jn < 4; jn++)
                    mma_f16(c[im][jn], a[im], blo[jn]);
        }
        __syncthreads();
    }
    #undef LOAD_STAGE

    // Epilogue: + bias; fp16 q/k/v; V also as tf32-rounded fp32 for O-phase.
    const int h      = (n0 + wn) >> 6;
    const int d_base = (n0 + wn) & 63;
    #pragma unroll
    for (int jn = 0; jn < 4; jn++) {
        int d = d_base + jn * 8 + gc * 2;
        float b0 = bias[n0 + wn + jn * 8 + gc * 2];
        float b1 = bias[n0 + wn + jn * 8 + gc * 2 + 1];
        #pragma unroll
        for (int im = 0; im < 4; im++) {
            int m = m0 + wm + im * 16 + gr;
            int b = m >> 9;
            int s = m & 511;
            size_t base = ((size_t)(b * H_ + h) * S_ + s) * D_ + d;
            float v0 = c[im][jn][0] + b0, v1 = c[im][jn][1] + b1;
            float v2 = c[im][jn][2] + b0, v3 = c[im][jn][3] + b1;
            *(__half2*)(outh + base) =
                __half2(__float2half_rn(v0), __float2half_rn(v1));
            *(__half2*)(outh + base + 8 * D_) =
                __half2(__float2half_rn(v2), __float2half_rn(v3));
            if (z == 2) {
                *(float2*)(g_v + base)          = make_float2(to_tf32(v0), to_tf32(v1));
                *(float2*)(g_v + base + 8 * D_) = make_float2(to_tf32(v2), to_tf32(v3));
            }
        }
    }
}

// ---------------------------------------------------------------------------
// Kernel 2: self-similarity scores (qq, kk, vv) via fp16 m16n8k16 MMA.
// Tiles in fp16 (half2 words): half the smem, half the LDS, half the MMAs
// vs tf32 — same 10-bit mantissa precision.
// Block: 64(q) x 128(k), 256 threads (8 warps 2x4). grid: (4, 8, 3*96).
// ---------------------------------------------------------------------------
__global__ void __launch_bounds__(256)
scores_sim(const float* __restrict__ mask, float* __restrict__ out_base)
{
    const int z    = blockIdx.z;
    const int type = 1 + z / BH_;       // 1:qq 2:kk 3:vv
    const int bh   = z % BH_;

    const __half* X = (type == 1) ? g_qh : ((type == 2) ? g_kh : g_vh);
    X += (size_t)bh * S_ * D_;

    float* out = out_base + (size_t)type * SC_ELEMS + (size_t)bh * S_ * S_;
    const float* mrow = mask + (size_t)(bh / H_) * S_;

    const int m0 = blockIdx.y * 64;
    const int n0 = blockIdx.x * 128;

    __shared__ __align__(16) uint32_t Xs[64][36];    // 32 k-pair words + pad
    __shared__ __align__(16) uint32_t Ys[128][36];

    const int tid = threadIdx.x;

    // row = 64 halves = 8 x 16B chunks
    #pragma unroll
    for (int r = 0; r < 2; r++) {
        int idx = tid + 256 * r;        // 0..511
        int row = idx >> 3;
        int ch  = idx & 7;
        *(uint4*)&Xs[row][ch * 4] =
            *(const uint4*)(X + (size_t)(m0 + row) * D_ + ch * 8);
    }
    #pragma unroll
    for (int r = 0; r < 4; r++) {
        int idx = tid + 256 * r;        // 0..1023
        int row = idx >> 3;
        int ch  = idx & 7;
        *(uint4*)&Ys[row][ch * 4] =
            *(const uint4*)(X + (size_t)(n0 + row) * D_ + ch * 8);
    }
    __syncthreads();

    const int lane = tid & 31;
    const int wid  = tid >> 5;
    const int wm   = (wid & 1) * 32;
    const int wn   = (wid >> 1) * 32;
    const int gr   = lane >> 2;
    const int gc   = lane & 3;

    float c[2][4][4];
    #pragma unroll
    for (int im = 0; im < 2; im++)
        #pragma unroll
        for (int jn = 0; jn < 4; jn++)
            #pragma unroll
            for (int r = 0; r < 4; r++) c[im][jn][r] = 0.0f;

    #pragma unroll
    for (int st = 0; st < 4; st++) {    // 4 k16 steps over D=64
        const int kp = st * 8 + gc;
        uint32_t a[2][4], b[4][2];
        #pragma unroll
        for (int im = 0; im < 2; im++) {
            int r0 = wm + im * 16 + gr;
            a[im][0] = Xs[r0    ][kp    ];
            a[im][1] = Xs[r0 + 8][kp    ];
            a[im][2] = Xs[r0    ][kp + 4];
            a[im][3] = Xs[r0 + 8][kp + 4];
        }
        #pragma unroll
        for (int jn = 0; jn < 4; jn++) {
            int n = wn + jn * 8 + gr;
            b[jn][0] = Ys[n][kp    ];
            b[jn][1] = Ys[n][kp + 4];
        }
        #pragma unroll
        for (int im = 0; im < 2; im++)
            #pragma unroll
            for (int jn = 0; jn < 4; jn++)
                mma_f16(c[im][jn], a[im], b[jn]);
    }

    #pragma unroll
    for (int im = 0; im < 2; im++) {
        #pragma unroll
        for (int jn = 0; jn < 4; jn++) {
            int row = m0 + wm + im * 16 + gr;
            int col = n0 + wn + jn * 8 + gc * 2;
            float mv0 = mrow[col], mv1 = mrow[col + 1];
            float2 o0 = make_float2(c[im][jn][0] * 0.125f + mv0,
                                    c[im][jn][1] * 0.125f + mv1);
            float2 o1 = make_float2(c[im][jn][2] * 0.125f + mv0,
                                    c[im][jn][3] * 0.125f + mv1);
            *(float2*)(out + (size_t)row * S_ + col)       = o0;
            *(float2*)(out + (size_t)(row + 8) * S_ + col) = o1;
        }
    }
}

// ---------------------------------------------------------------------------
// Kernel 3: fused qk-scores + softmax + P@V.
// S-phase: fp16 m16n8k16 (Q,K fp16 -> half the MMAs/LDS/smem, aq regs 32->16).
// O-phase: validated tf32 path (P tf32 in fp32 smem, V fp32 tf32-rounded).
// 128 threads = 4 warps. grid: (8, 96).
// ---------------------------------------------------------------------------
__global__ void __launch_bounds__(128)
flash_attn(const float* __restrict__ mask, float* __restrict__ sout_base,
           float* __restrict__ ctx)
{
    const int bh = blockIdx.y;
    const int q0 = blockIdx.x * 64;
    const int b  = bh / H_;
    const int h  = bh - b * H_;
    const __half* Qp = g_qh + (size_t)bh * S_ * D_;
    const __half* Kp = g_kh + (size_t)bh * S_ * D_;
    const float*  Vp = g_v  + (size_t)bh * S_ * D_;
    float* sout = sout_base + (size_t)bh * S_ * S_;
    const float* mrow = mask + (size_t)b * S_;

    // QPs: first holds Q fp16 tile (64x36 u32 region), then reused as P fp32.
    __shared__ __align__(16) float QPs[64][68];
    __shared__ __align__(16) uint32_t Ku[64][36];
    __shared__ float Vs[64][72];

    uint32_t* QPu = (uint32_t*)&QPs[0][0];

    const int tid  = threadIdx.x;
    const int lane = tid & 31;
    const int w    = tid >> 5;
    const int gr   = lane >> 2;
    const int gc   = lane & 3;

    // Load Q fp16 tile (64 rows x 8 chunks)
    #pragma unroll
    for (int r = 0; r < 4; r++) {
        int idx = tid + 128 * r;        // 0..511
        int row = idx >> 3;
        int ch  = idx & 7;
        *(uint4*)&QPu[row * 36 + ch * 4] =
            *(const uint4*)(Qp + (size_t)(q0 + row) * D_ + ch * 8);
    }
    __syncthreads();

    // Build fp16 A-fragments for all 4 k16 steps (regs: 16)
    uint32_t aq[4][4];
    #pragma unroll
    for (int st = 0; st < 4; st++) {
        int kp = st * 8 + gc;
        int r0 = w * 16 + gr;
        aq[st][0] = QPu[ r0      * 36 + kp    ];
        aq[st][1] = QPu[(r0 + 8) * 36 + kp    ];
        aq[st][2] = QPu[ r0      * 36 + kp + 4];
        aq[st][3] = QPu[(r0 + 8) * 36 + kp + 4];
    }

    float o[8][4];
    #pragma unroll
    for (int jd = 0; jd < 8; jd++)
        #pragma unroll
        for (int r = 0; r < 4; r++) o[jd][r] = 0.0f;

    float m0 = -1e30f, m1 = -1e30f, l0 = 0.0f, l1 = 0.0f;
    const int rowg = q0 + w * 16 + gr;

    for (int kt = 0; kt < 8; kt++) {
        // K fp16 tile: 512 chunks; V fp32 tile: 1024 chunks
        #pragma unroll
        for (int r = 0; r < 4; r++) {
            int idx = tid + 128 * r;
            int row = idx >> 3;
            int ch  = idx & 7;
            *(uint4*)&Ku[row][ch * 4] =
                *(const uint4*)(Kp + (size_t)(kt*64 + row) * D_ + ch * 8);
        }
        #pragma unroll
        for (int r = 0; r < 8; r++) {
            int idx = tid + 128 * r;
            int row = idx >> 4;
            int q   = idx & 15;
            *(float4*)&Vs[row][q * 4] =
                *(const float4*)(Vp + (size_t)(kt*64 + row) * D_ + q * 4);
        }
        __syncthreads();

        // S = Q @ K^T  (fp16, 4 k16 steps)
        float s[8][4];
        #pragma unroll
        for (int jn = 0; jn < 8; jn++) {
            #pragma unroll
            for (int r = 0; r < 4; r++) s[jn][r] = 0.0f;
            #pragma unroll
            for (int st = 0; st < 4; st++) {
                int kp = st * 8 + gc;
                uint32_t bv[2];
                bv[0] = Ku[jn*8 + gr][kp    ];
                bv[1] = Ku[jn*8 + gr][kp + 4];
                mma_f16(s[jn], aq[st], bv);
            }
        }

        float mx0 = -1e30f, mx1 = -1e30f;
        #pragma unroll
        for (int jn = 0; jn < 8; jn++) {
            int col = kt*64 + jn*8 + gc*2;
            float mv0 = mrow[col], mv1 = mrow[col + 1];
            s[jn][0] = s[jn][0]*0.125f + mv0;  s[jn][1] = s[jn][1]*0.125f + mv1;
            s[jn][2] = s[jn][2]*0.125f + mv0;  s[jn][3] = s[jn][3]*0.125f + mv1;
            *(float2*)(sout + (size_t)rowg       * S_ + col) = make_float2(s[jn][0], s[jn][1]);
            *(float2*)(sout + (size_t)(rowg + 8) * S_ + col) = make_float2(s[jn][2], s[jn][3]);
            mx0 = fmaxf(mx0, fmaxf(s[jn][0], s[jn][1]));
            mx1 = fmaxf(mx1, fmaxf(s[jn][2], s[jn][3]));
        }
        mx0 = fmaxf(mx0, __shfl_xor_sync(0xffffffffu, mx0, 1));
        mx0 = fmaxf(mx0, __shfl_xor_sync(0xffffffffu, mx0, 2));
        mx1 = fmaxf(mx1, __shfl_xor_sync(0xffffffffu, mx1, 1));
        mx1 = fmaxf(mx1, __shfl_xor_sync(0xffffffffu, mx1, 2));

        float mn0 = fmaxf(m0, mx0), mn1 = fmaxf(m1, mx1);
        float sc0 = __expf(m0 - mn0), sc1 = __expf(m1 - mn1);

        float ps0 = 0.0f, ps1 = 0.0f;
        #pragma unroll
        for (int jn = 0; jn < 8; jn++) {
            float p0 = __expf(s[jn][0] - mn0), p1 = __expf(s[jn][1] - mn0);
            float p2 = __expf(s[jn][2] - mn1), p3 = __expf(s[jn][3] - mn1);
            ps0 += p0 + p1;  ps1 += p2 + p3;
            int col = jn*8 + gc*2;
            int r0  = w*16 + gr;
            *(float2*)&QPs[r0    ][col] = make_float2(to_tf32(p0), to_tf32(p1));
            *(float2*)&QPs[r0 + 8][col] = make_float2(to_tf32(p2), to_tf32(p3));
        }
        ps0 += __shfl_xor_sync(0xffffffffu, ps0, 1);
        ps0 += __shfl_xor_sync(0xffffffffu, ps0, 2);
        ps1 += __shfl_xor_sync(0xffffffffu, ps1, 1);
        ps1 += __shfl_xor_sync(0xffffffffu, ps1, 2);
        l0 = l0 * sc0 + ps0;  l1 = l1 * sc1 + ps1;
        m0 = mn0;  m1 = mn1;

        #pragma unroll
        for (int jd = 0; jd < 8; jd++) {
            o[jd][0] *= sc0;  o[jd][1] *= sc0;
            o[jd][2] *= sc1;  o[jd][3] *= sc1;
        }
        __syncwarp();

        // O += P @ V  (tf32, validated path)
        #pragma unroll
        for (int ks = 0; ks < 8; ks++) {
            uint32_t ap[4];
            int r0 = w*16 + gr;
            ap[0] = __float_as_uint(QPs[r0    ][8*ks + gc    ]);
            ap[1] = __float_as_uint(QPs[r0 + 8][8*ks + gc    ]);
            ap[2] = __float_as_uint(QPs[r0    ][8*ks + gc + 4]);
            ap[3] = __float_as_uint(QPs[r0 + 8][8*ks + gc + 4]);
            #pragma unroll
            for (int jd = 0; jd < 8; jd++) {
                uint32_t bv[2];
                bv[0] = __float_as_uint(Vs[8*ks + gc    ][jd*8 + gr]);
                bv[1] = __float_as_uint(Vs[8*ks + gc + 4][jd*8 + gr]);
                mma_tf32(o[jd], ap, bv);
            }
        }
        __syncthreads();
    }

    float i0 = 1.0f / l0, i1 = 1.0f / l1;
    #pragma unroll
    for (int jd = 0; jd < 8; jd++) {
        int d = jd*8 + gc*2;
        float* op = ctx + ((size_t)(b * S_ + rowg) * HID_ + h * D_ + d);
        *(float2*)op              = make_float2(o[jd][0] * i0, o[jd][1] * i0);
        *(float2*)(op + 8 * HID_) = make_float2(o[jd][2] * i1, o[jd][3] * i1);
    }
}

// ---------------------------------------------------------------------------
extern "C" void kernel_launch(void* const* d_in, const int* in_sizes, int n_in,
                              void* d_out, int out_size)
{
    const float* hid  = (const float*)d_in[0];
    const float* mask = (const float*)d_in[1];
    const float* Wq   = (const float*)d_in[2];
    const float* bq   = (const float*)d_in[3];
    const float* Wk   = (const float*)d_in[4];
    const float* bk   = (const float*)d_in[5];
    const float* Wv   = (const float*)d_in[6];
    const float* bv   = (const float*)d_in[7];
    float* out = (float*)d_out;

    // 0) prep: hidden -> fp16 hi plane; W -> fp16 (hi,lo) pairs
    split_prep<<<PREP_BLOCKS, 256>>>(hid, Wq, Wk, Wv);

    // 1) Q,K,V projections (fp16 2-term MMA; fp16 q/k/v outputs + fp32 V)
    qkv_mma<<<dim3(HID_ / 128, BS_ / 128, 3), 256>>>(bq, bk, bv);

    // 2) qq / kk / vv self-similarity scores (fp16 MMA)
    scores_sim<<<dim3(S_ / 128, S_ / 64, 3 * BH_), 256>>>(mask, out + CTX_ELEMS);

    // 3) fused qk scores + softmax + P@V -> scores(qk) region + ctx
    flash_attn<<<dim3(S_ / 64, BH_), 128>>>(mask, out + CTX_ELEMS, out);
}